// round 16
// baseline (speedup 1.0000x reference)
#include <cuda_runtime.h>
#include <cuda_fp16.h>
#include <math.h>
#include <stdint.h>

#define NB 32
#define NCQ 256
#define NCC 3
#define NINTER 128
#define NHW 1024
#define NHC 224
#define GN_N (NCQ*NHW)

// ---------------- scratch (static device memory, no allocs) ----------------
__device__ __half g_qT[NB*NHW*NINTER];              // [b][i][c']
__device__ __half g_kT[NB*NHW*NINTER];              // [b][j][c']
__device__ __half g_v [NB*NCQ*NHW];                 // [b][c][j]
__device__ __half g_F [NB*NCQ*NHW];                 // fused F[b][o][i] (fp16)
__device__ __half g_queryT[NB*NHW*NCQ];             // [b][i][c]
__device__ __half g_Wp[NCQ*NCQ];
__device__ float  g_sums[NB*2];

__device__ __forceinline__ uint32_t pk2(float a, float b) {
    __half2 h = __floats2half2_rn(a, b);
    return *(uint32_t*)&h;
}
__device__ __forceinline__ float2 up2(uint32_t u) {
    __half2 h = *(__half2*)&u;
    return __half22float2(h);
}

__device__ __forceinline__ void mma_f16(float* d, uint32_t a0, uint32_t a1, uint32_t a2,
                                        uint32_t a3, uint32_t b0, uint32_t b1) {
    asm volatile(
        "mma.sync.aligned.m16n8k16.row.col.f32.f16.f16.f32 "
        "{%0,%1,%2,%3}, {%4,%5,%6,%7}, {%8,%9}, {%0,%1,%2,%3};"
        : "+f"(d[0]), "+f"(d[1]), "+f"(d[2]), "+f"(d[3])
        : "r"(a0), "r"(a1), "r"(a2), "r"(a3), "r"(b0), "r"(b1));
}

__device__ __forceinline__ void ldsm4(uint32_t& r0, uint32_t& r1, uint32_t& r2, uint32_t& r3,
                                      uint32_t adr) {
    asm volatile("ldmatrix.sync.aligned.m8n8.x4.shared.b16 {%0,%1,%2,%3}, [%4];"
                 : "=r"(r0), "=r"(r1), "=r"(r2), "=r"(r3) : "r"(adr));
}

__device__ __forceinline__ void cpa16(void* dst, const void* src) {
    uint32_t d = (uint32_t)__cvta_generic_to_shared(dst);
    asm volatile("cp.async.cg.shared.global [%0], [%1], 16;" :: "r"(d), "l"(src));
}
#define CP_COMMIT asm volatile("cp.async.commit_group;")

// ---------------- merged preprocessing kernel --------------------------------------
// sections: [0,256) qproj GEMM (+queryT emit); [256,768) resize+k/v; [768,800) Wp conv
#define HP 20    // A-tile pitch (u32): 16 data + 4 pad
#define WPP 132  // full-Wq smem pitch (u32): 128 data + 4 pad
#define PRE_SMEM ((128 * HP + 128 * WPP) * 4)
__global__ __launch_bounds__(256)
void pre_kernel(const float* __restrict__ query, const float* __restrict__ ctx,
                const float* __restrict__ Wq, const float* __restrict__ bq,
                const float* __restrict__ Wk, const float* __restrict__ bk,
                const float* __restrict__ Wv, const float* __restrict__ bv,
                const float* __restrict__ Wp) {
    extern __shared__ uint32_t sm_u[];
    int blk = blockIdx.x;
    int tid = threadIdx.x;

    if (blk < 256) {
        // qproj GEMM (M=128 i, N=128 c', K=256 c); Wq resident in smem; A prefetched.
        uint32_t* As  = sm_u;               // 128 x HP
        uint32_t* WqS = sm_u + 128 * HP;    // 128 x WPP (full Wq fp16)
        int b = blk >> 3, i0 = (blk & 7) * 128;
        const float* qb = query + (size_t)b * NCQ * NHW;

        int lane = tid & 31, wid = tid >> 5;
        int wm = wid >> 2, wn = wid & 3;
        int gid = lane >> 2, tig = lane & 3;
        int lrow8 = (lane & 7) | (((lane >> 3) & 1) << 3);
        int kblk4 = (lane >> 4) << 2;
        uint32_t As0 = (uint32_t)__cvta_generic_to_shared(As);
        uint32_t Wq0 = (uint32_t)__cvta_generic_to_shared(WqS);

        // one-time: full Wq fp32 -> fp16 smem
#pragma unroll
        for (int it = 0; it < 16; it++) {
            int id = tid + it * 256;
            int n = id >> 5, s8 = (id & 31) * 8;
            float4 w0 = *(const float4*)&Wq[n * 256 + s8];
            float4 w1 = *(const float4*)&Wq[n * 256 + s8 + 4];
            uint32_t* d = &WqS[n * WPP + (s8 >> 1)];
            d[0] = pk2(w0.x, w0.y); d[1] = pk2(w0.z, w0.w);
            d[2] = pk2(w1.x, w1.y); d[3] = pk2(w1.z, w1.w);
        }

        float acc[4][4][4];
#pragma unroll
        for (int i = 0; i < 4; i++)
#pragma unroll
            for (int j = 0; j < 4; j++)
#pragma unroll
                for (int r = 0; r < 4; r++) acc[i][j][r] = 0.f;

        int m = tid & 127, kg = (tid >> 7) * 4;
        int qrow = tid >> 1, qcu = (tid & 1) * 8;
        uint32_t* qTout = (uint32_t*)(g_queryT + ((size_t)b * NHW + i0 + qrow) * NCQ) + qcu;

        float ar[4][4];
        // prefetch A tile 0
#pragma unroll
        for (int pass = 0; pass < 4; pass++) {
            int kb = pass * 8 + kg;
            const float* src = &qb[(size_t)kb * NHW + i0 + m];
            ar[pass][0] = src[0]; ar[pass][1] = src[NHW];
            ar[pass][2] = src[2 * NHW]; ar[pass][3] = src[3 * NHW];
        }

        for (int kt = 0; kt < 8; kt++) {
            __syncthreads();   // As free (mma kt-1 done); also fences WqS fill at kt=0
#pragma unroll
            for (int pass = 0; pass < 4; pass++) {
                int kb = pass * 8 + kg;
                As[m * HP + (kb >> 1)]     = pk2(ar[pass][0], ar[pass][1]);
                As[m * HP + (kb >> 1) + 1] = pk2(ar[pass][2], ar[pass][3]);
            }
            __syncthreads();
            if (kt < 7) {      // prefetch A tile kt+1 (retires during mma below)
#pragma unroll
                for (int pass = 0; pass < 4; pass++) {
                    int kb = pass * 8 + kg;
                    const float* src = &qb[(size_t)((kt + 1) * 32 + kb) * NHW + i0 + m];
                    ar[pass][0] = src[0]; ar[pass][1] = src[NHW];
                    ar[pass][2] = src[2 * NHW]; ar[pass][3] = src[3 * NHW];
                }
            }
            {   // emit transposed queryT tile (fp16) straight from As
                uint4 v0 = *(uint4*)&As[qrow * HP + qcu];
                uint4 v1 = *(uint4*)&As[qrow * HP + qcu + 4];
                *(uint4*)(qTout + kt * 16)     = v0;
                *(uint4*)(qTout + kt * 16 + 4) = v1;
            }
#pragma unroll
            for (int ks = 0; ks < 2; ks++) {
                int colA = ks * 8 + kblk4;
                int colB = kt * 16 + ks * 8 + kblk4;
                uint32_t afr[4][4], bfr[4][2];
#pragma unroll
                for (int mt = 0; mt < 4; mt++) {
                    int row = wm * 64 + mt * 16 + lrow8;
                    ldsm4(afr[mt][0], afr[mt][1], afr[mt][2], afr[mt][3],
                          As0 + (uint32_t)(row * HP + colA) * 4);
                }
#pragma unroll
                for (int p = 0; p < 2; p++) {
                    int row = wn * 32 + p * 16 + lrow8;
                    ldsm4(bfr[2*p][0], bfr[2*p+1][0], bfr[2*p][1], bfr[2*p+1][1],
                          Wq0 + (uint32_t)(row * WPP + colB) * 4);
                }
#pragma unroll
                for (int mt = 0; mt < 4; mt++)
#pragma unroll
                    for (int nt = 0; nt < 4; nt++)
                        mma_f16(acc[mt][nt], afr[mt][0], afr[mt][1], afr[mt][2], afr[mt][3],
                                bfr[nt][0], bfr[nt][1]);
            }
        }
        uint32_t* C = (uint32_t*)(g_qT + ((size_t)b * NHW + i0) * NINTER);
#pragma unroll
        for (int mt = 0; mt < 4; mt++) {
#pragma unroll
            for (int nt = 0; nt < 4; nt++) {
                int row0 = wm * 64 + mt * 16 + gid;
                int col  = wn * 32 + nt * 8 + tig * 2;
                float bn0 = bq[col], bn1 = bq[col + 1];
#pragma unroll
                for (int h = 0; h < 2; h++) {
                    int row = row0 + h * 8;
                    C[(row * NINTER + col) >> 1] =
                        pk2(acc[mt][nt][h * 2] + bn0, acc[mt][nt][h * 2 + 1] + bn1);
                }
            }
        }
    } else if (blk < 768) {
        // resize + k/v projection
        float* sctx = (float*)sm_u;
        float* sWk  = sctx + 192;
        float* sbk  = sWk + 384;
        float* sWv  = sbk + 128;
        float* sbv  = sWv + 768;
        int s = blk - 256;
        int b = s >> 4, j0 = (s & 15) * 64;

        for (int i = tid; i < NINTER * 3; i += 256) sWk[i] = Wk[i];
        for (int i = tid; i < NCQ * 3; i += 256)    sWv[i] = Wv[i];
        if (tid < NINTER) sbk[tid] = bk[tid];
        if (tid < NCQ)    sbv[tid] = bv[tid];

        if (tid < NCC * 64) {
            int c = tid >> 6, jj = tid & 63;
            int p = j0 + jj;
            int y = p >> 5, x = p & 31;
            float sy = 7.f * y + 3.f;
            float sx = 7.f * x + 3.f;
            int y0 = (int)floorf(sy), x0 = (int)floorf(sx);
            float fy = sy - y0, fx = sx - x0;
            int y1 = min(y0 + 1, NHC - 1), x1 = min(x0 + 1, NHC - 1);
            y0 = max(y0, 0); x0 = max(x0, 0);
            const float* base = ctx + ((size_t)b * NCC + c) * NHC * NHC;
            float v00 = base[y0 * NHC + x0], v01 = base[y0 * NHC + x1];
            float v10 = base[y1 * NHC + x0], v11 = base[y1 * NHC + x1];
            sctx[c * 64 + jj] = (1.f - fy) * ((1.f - fx) * v00 + fx * v01)
                              + fy * ((1.f - fx) * v10 + fx * v11);
        }
        __syncthreads();

        __half* kout = g_kT + ((size_t)b * NHW + j0) * NINTER;
#pragma unroll 4
        for (int o = tid; o < 64 * NINTER; o += 256) {
            int jj = o >> 7, c = o & 127;
            kout[(size_t)jj * NINTER + c] = __float2half_rn(
                sbk[c] + sWk[c*3]*sctx[jj] + sWk[c*3+1]*sctx[64+jj] + sWk[c*3+2]*sctx[128+jj]);
        }
        __half* vout = g_v + (size_t)b * NCQ * NHW + j0;
#pragma unroll 4
        for (int o = tid; o < NCQ * 64; o += 256) {
            int c = o >> 6, jj = o & 63;
            vout[(size_t)c * NHW + jj] = __float2half_rn(
                sbv[c] + sWv[c*3]*sctx[jj] + sWv[c*3+1]*sctx[64+jj] + sWv[c*3+2]*sctx[128+jj]);
        }
    } else {
        // Wp convert + sums zero
        int base = (blk - 768) * 2048;
        for (int j = tid; j < 2048; j += 256)
            g_Wp[base + j] = __float2half_rn(Wp[base + j]);
        if (blk == 768 && tid < NB * 2) g_sums[tid] = 0.f;
    }
}

// ---------------- flash v6: attention + fused conv (Wp) in one kernel --------------
#define F_SMEM_BYTES (32768 * 4)

__global__ __launch_bounds__(256, 1)
void flash_kernel(const __half* __restrict__ qT, const __half* __restrict__ kT,
                  const __half* __restrict__ v, const __half* __restrict__ queryT,
                  const float* __restrict__ bp, __half* __restrict__ F) {
    extern __shared__ uint32_t smu[];
    uint32_t* Qs = smu;                    // 128 x 64
    uint32_t* Ks = Qs + 128 * 64;          // 2 x 64 x 64
    uint32_t* Vs = Ks + 2 * 64 * 64;       // 2 x 256 x 32
    uint32_t* WpS = smu;                   // epilogue: 2 x 256 x HP
    uint32_t* Xs  = smu + 2 * 256 * HP;    // epilogue: 128 x 128

    uint32_t Qs_b = (uint32_t)__cvta_generic_to_shared(Qs);
    uint32_t Ks_b = (uint32_t)__cvta_generic_to_shared(Ks);
    uint32_t Vs_b = (uint32_t)__cvta_generic_to_shared(Vs);
    uint32_t Wp_b = (uint32_t)__cvta_generic_to_shared(WpS);
    uint32_t Xs_b = (uint32_t)__cvta_generic_to_shared(Xs);

    int b = blockIdx.y, i0 = blockIdx.x * 128;
    const __half* qTb = qT + ((size_t)b * NHW + i0) * NINTER;
    const __half* kTb = kT + (size_t)b * NHW * NINTER;
    const __half* vb  = v  + (size_t)b * NCQ * NHW;

    int tid = threadIdx.x, lane = tid & 31, w = tid >> 5;
    int gid = lane >> 2, tig = lane & 3;
    int lrow8 = (lane & 7) | (((lane >> 3) & 1) << 3);
    int kblk4 = (lane >> 4) << 2;
    int swl = (lane & 7) << 2;

#pragma unroll
    for (int it = 0; it < 8; it++) {
        int id = tid + it * 256;
        int r = id >> 4, c4 = (id & 15) << 2;
        uint4 vq = *(const uint4*)&qTb[(size_t)r * NINTER + c4 * 2];
        *(uint4*)&Qs[r * 64 + (c4 ^ ((r & 7) << 2))] = vq;
    }

#pragma unroll
    for (int it = 0; it < 4; it++) {
        int id = tid + it * 256;
        int r = id >> 4, c4 = (id & 15) << 2;
        cpa16(&Ks[r * 64 + (c4 ^ ((r & 7) << 2))], &kTb[(size_t)r * NINTER + c4 * 2]);
    }
#pragma unroll
    for (int it = 0; it < 8; it++) {
        int id = tid + it * 256;
        int r = id >> 3, c4 = (id & 7) << 2;
        cpa16(&Vs[r * 32 + (c4 ^ ((r & 7) << 2))], &vb[(size_t)r * NHW + c4 * 2]);
    }
    CP_COMMIT;

    float oa[32][4];
#pragma unroll
    for (int nt = 0; nt < 32; nt++)
#pragma unroll
        for (int r = 0; r < 4; r++) oa[nt][r] = 0.f;
    float l0 = 0.f, l1 = 0.f, m0r = -1e30f, m1r = -1e30f;

    uint32_t qadr = Qs_b + (uint32_t)((w * 16 + lrow8) * 64) * 4;
    uint32_t kadr = Ks_b + (uint32_t)(lrow8 * 64) * 4;
    uint32_t vadr = Vs_b + (uint32_t)(lrow8 * 32) * 4;

    for (int t = 0; t < 16; t++) {
        int buf = t & 1;
        uint32_t kOff = (uint32_t)buf * (64 * 64 * 4);
        uint32_t vOff = (uint32_t)buf * (256 * 32 * 4);

        __syncthreads();
        if (t < 15) {
            int j0 = (t + 1) * 64;
            uint32_t* kd = &Ks[(buf ^ 1) * 64 * 64];
            uint32_t* vd = &Vs[(buf ^ 1) * 256 * 32];
#pragma unroll
            for (int it = 0; it < 4; it++) {
                int id = tid + it * 256;
                int r = id >> 4, c4 = (id & 15) << 2;
                cpa16(&kd[r * 64 + (c4 ^ ((r & 7) << 2))],
                      &kTb[(size_t)(j0 + r) * NINTER + c4 * 2]);
            }
#pragma unroll
            for (int it = 0; it < 8; it++) {
                int id = tid + it * 256;
                int r = id >> 3, c4 = (id & 7) << 2;
                cpa16(&vd[r * 32 + (c4 ^ ((r & 7) << 2))],
                      &vb[(size_t)r * NHW + j0 + c4 * 2]);
            }
            CP_COMMIT;
            asm volatile("cp.async.wait_group 1;");
        } else {
            asm volatile("cp.async.wait_group 0;");
        }
        __syncthreads();

        float sc[8][4];
#pragma unroll
        for (int nt = 0; nt < 8; nt++)
#pragma unroll
            for (int r = 0; r < 4; r++) sc[nt][r] = 0.f;
#pragma unroll
        for (int s = 0; s < 8; s++) {
            uint32_t cb = (uint32_t)(((s * 8 + kblk4) ^ swl) * 4);
            uint32_t a0, a1, a2, a3;
            ldsm4(a0, a1, a2, a3, qadr + cb);
#pragma unroll
            for (int g = 0; g < 4; g++) {
                uint32_t r0, r1, r2, r3;
                ldsm4(r0, r1, r2, r3, kadr + kOff + (uint32_t)(g * 16 * 64 * 4) + cb);
                mma_f16(sc[2*g],   a0, a1, a2, a3, r0, r2);
                mma_f16(sc[2*g+1], a0, a1, a2, a3, r1, r3);
            }
        }

        float mx0 = -1e30f, mx1 = -1e30f;
#pragma unroll
        for (int nt = 0; nt < 8; nt++) {
            mx0 = fmaxf(mx0, fmaxf(sc[nt][0], sc[nt][1]));
            mx1 = fmaxf(mx1, fmaxf(sc[nt][2], sc[nt][3]));
        }
        mx0 = fmaxf(mx0, __shfl_xor_sync(0xffffffffu, mx0, 1));
        mx0 = fmaxf(mx0, __shfl_xor_sync(0xffffffffu, mx0, 2));
        mx1 = fmaxf(mx1, __shfl_xor_sync(0xffffffffu, mx1, 1));
        mx1 = fmaxf(mx1, __shfl_xor_sync(0xffffffffu, mx1, 2));
        float mn0 = fmaxf(m0r, mx0), mn1 = fmaxf(m1r, mx1);
        float al0 = __expf(m0r - mn0), al1 = __expf(m1r - mn1);
        m0r = mn0; m1r = mn1;

        uint32_t pa[4][4];
        float s0 = 0.f, s1 = 0.f;
#pragma unroll
        for (int nt = 0; nt < 8; nt++) {
            float e0 = __expf(sc[nt][0] - mn0);
            float e1 = __expf(sc[nt][1] - mn0);
            float e2 = __expf(sc[nt][2] - mn1);
            float e3 = __expf(sc[nt][3] - mn1);
            s0 += e0 + e1; s1 += e2 + e3;
            pa[nt >> 1][(nt & 1) * 2]     = pk2(e0, e1);
            pa[nt >> 1][(nt & 1) * 2 + 1] = pk2(e2, e3);
        }
        l0 = l0 * al0 + s0;
        l1 = l1 * al1 + s1;

        if (al0 != 1.f || al1 != 1.f) {
#pragma unroll
            for (int nt = 0; nt < 32; nt++) {
                oa[nt][0] *= al0; oa[nt][1] *= al0;
                oa[nt][2] *= al1; oa[nt][3] *= al1;
            }
        }

#pragma unroll
        for (int k = 0; k < 4; k++) {
            uint32_t cb = (uint32_t)(((k * 8 + kblk4) ^ swl) * 4);
#pragma unroll
            for (int g = 0; g < 16; g++) {
                uint32_t r0, r1, r2, r3;
                ldsm4(r0, r1, r2, r3, vadr + vOff + (uint32_t)(g * 16 * 32 * 4) + cb);
                mma_f16(oa[2*g],   pa[k][0], pa[k][1], pa[k][2], pa[k][3], r0, r2);
                mma_f16(oa[2*g+1], pa[k][0], pa[k][1], pa[k][2], pa[k][3], r1, r3);
            }
        }
    }

    l0 += __shfl_xor_sync(0xffffffffu, l0, 1);
    l0 += __shfl_xor_sync(0xffffffffu, l0, 2);
    l1 += __shfl_xor_sync(0xffffffffu, l1, 1);
    l1 += __shfl_xor_sync(0xffffffffu, l1, 2);
    float inv0 = 1.f / l0, inv1 = 1.f / l1;

    // -------- stage X = O/l + residual into smem (fp16, XOR-swizzled) --------
    __syncthreads();
    {
        int r0 = w * 16 + gid, r1 = r0 + 8;
        const uint32_t* qres = (const uint32_t*)(queryT + ((size_t)b * NHW + i0) * NCQ);
        int x0m = (r0 & 7) << 2, x1m = (r1 & 7) << 2;
#pragma unroll
        for (int nt = 0; nt < 32; nt++) {
            int cu = nt * 4 + tig;
            float2 q0 = up2(qres[r0 * 128 + cu]);
            float2 q1 = up2(qres[r1 * 128 + cu]);
            Xs[r0 * 128 + (cu ^ x0m)] = pk2(oa[nt][0] * inv0 + q0.x, oa[nt][1] * inv0 + q0.y);
            Xs[r1 * 128 + (cu ^ x1m)] = pk2(oa[nt][2] * inv1 + q1.x, oa[nt][3] * inv1 + q1.y);
        }
    }
#pragma unroll
    for (int it = 0; it < 4; it++) {
        int id = tid + it * 256;
        int r = id >> 2, cs = (id & 3) * 4;
        cpa16(&WpS[r * HP + cs], g_Wp + r * 256 + cs * 2);
    }
    CP_COMMIT;
    asm volatile("cp.async.wait_group 0;");
    __syncthreads();

    // -------- inline GEMM: F[o][i0+i] = Wp[o][:] . X[i][:] + bp[o] --------
    int wm3 = w >> 1, wn3 = w & 1;
    float acc[4][8][4];
#pragma unroll
    for (int i = 0; i < 4; i++)
#pragma unroll
        for (int j = 0; j < 8; j++)
#pragma unroll
            for (int r = 0; r < 4; r++) acc[i][j][r] = 0.f;

    for (int kt = 0; kt < 8; kt++) {
        int buf = kt & 1;
        if (kt < 7) {
            uint32_t* wd = &WpS[(buf ^ 1) * 256 * HP];
            const __half* wsrc = g_Wp + (kt + 1) * 32;
#pragma unroll
            for (int it = 0; it < 4; it++) {
                int id = tid + it * 256;
                int r = id >> 2, cs = (id & 3) * 4;
                cpa16(&wd[r * HP + cs], wsrc + r * 256 + cs * 2);
            }
            CP_COMMIT;
        }
        uint32_t wBase = Wp_b + (uint32_t)(buf * 256 * HP) * 4;
#pragma unroll
        for (int ks = 0; ks < 2; ks++) {
            int colA = ks * 8 + kblk4;
            int colB = (kt * 16 + ks * 8 + kblk4) ^ swl;
            uint32_t afr[4][4], bfr[8][2];
#pragma unroll
            for (int mt = 0; mt < 4; mt++) {
                int row = wm3 * 64 + mt * 16 + lrow8;
                ldsm4(afr[mt][0], afr[mt][1], afr[mt][2], afr[mt][3],
                      wBase + (uint32_t)(row * HP + colA) * 4);
            }
#pragma unroll
            for (int p = 0; p < 4; p++) {
                int row = wn3 * 64 + p * 16 + lrow8;
                ldsm4(bfr[2*p][0], bfr[2*p+1][0], bfr[2*p][1], bfr[2*p+1][1],
                      Xs_b + (uint32_t)(row * 128 + colB) * 4);
            }
#pragma unroll
            for (int mt = 0; mt < 4; mt++)
#pragma unroll
                for (int nt = 0; nt < 8; nt++)
                    mma_f16(acc[mt][nt], afr[mt][0], afr[mt][1], afr[mt][2], afr[mt][3],
                            bfr[nt][0], bfr[nt][1]);
        }
        if (kt < 7) {
            asm volatile("cp.async.wait_group 0;");
            __syncthreads();
        }
    }

    // -------- epilogue: bias + GN stats + fp16 F store --------
    __shared__ float rs[8], rq[8];
    float ls = 0.f, lq = 0.f;
    __half* Fb = F + (size_t)b * NCQ * NHW + i0;
#pragma unroll
    for (int mt = 0; mt < 4; mt++) {
#pragma unroll
        for (int nt = 0; nt < 8; nt++) {
            int row0 = wm3 * 64 + mt * 16 + gid;
            int col  = wn3 * 64 + nt * 8 + tig * 2;
#pragma unroll
            for (int h = 0; h < 2; h++) {
                int row = row0 + h * 8;
                float bm = bp[row];
                float x = acc[mt][nt][h * 2] + bm, y = acc[mt][nt][h * 2 + 1] + bm;
                ls += x + y; lq += x * x + y * y;
                *(uint32_t*)(Fb + (size_t)row * NHW + col) = pk2(x, y);
            }
        }
    }
#pragma unroll
    for (int o = 16; o; o >>= 1) {
        ls += __shfl_xor_sync(0xffffffffu, ls, o);
        lq += __shfl_xor_sync(0xffffffffu, lq, o);
    }
    if (lane == 0) { rs[w] = ls; rq[w] = lq; }
    __syncthreads();
    if (tid == 0) {
        float ts = 0.f, tq = 0.f;
#pragma unroll
        for (int i = 0; i < 8; i++) { ts += rs[i]; tq += rq[i]; }
        atomicAdd(&g_sums[b * 2], ts);
        atomicAdd(&g_sums[b * 2 + 1], tq);
    }
}

// ---------------- normalize + affine -> out (half F in, float4 out) -----------------
__global__ void norm_kernel(const float* __restrict__ gamma, const float* __restrict__ beta,
                            float* __restrict__ out) {
    int idx = (blockIdx.x * blockDim.x + threadIdx.x) * 4;
    int b = idx >> 18;
    int o = (idx >> 10) & 255;
    float s = g_sums[b * 2], s2 = g_sums[b * 2 + 1];
    const float n = (float)GN_N;
    float mu = s / n;
    float var = s2 / n - mu * mu;
    float rstd = rsqrtf(var + 1e-5f);
    float ga = gamma[o] * rstd, be = beta[o] - mu * ga;
    uint2 fh = *(const uint2*)&((const uint32_t*)g_F)[idx >> 1];
    float2 f01 = up2(fh.x), f23 = up2(fh.y);
    float4 r;
    r.x = f01.x * ga + be; r.y = f01.y * ga + be;
    r.z = f23.x * ga + be; r.w = f23.y * ga + be;
    *(float4*)&out[idx] = r;
}

// ---------------- launch --------------------------------------------------------------
extern "C" void kernel_launch(void* const* d_in, const int* in_sizes, int n_in,
                              void* d_out, int out_size) {
    const float* query = (const float*)d_in[0];
    const float* ctx   = (const float*)d_in[1];
    const float* Wq = (const float*)d_in[2];  const float* bq = (const float*)d_in[3];
    const float* Wk = (const float*)d_in[4];  const float* bk = (const float*)d_in[5];
    const float* Wv = (const float*)d_in[6];  const float* bv = (const float*)d_in[7];
    const float* Wp = (const float*)d_in[8];  const float* bp = (const float*)d_in[9];
    const float* gamma = (const float*)d_in[10];
    const float* beta  = (const float*)d_in[11];
    float* out = (float*)d_out;

    __half *p_qT, *p_kT, *p_v, *p_queryT, *p_F;
    cudaGetSymbolAddress((void**)&p_qT, g_qT);
    cudaGetSymbolAddress((void**)&p_kT, g_kT);
    cudaGetSymbolAddress((void**)&p_v, g_v);
    cudaGetSymbolAddress((void**)&p_F, g_F);
    cudaGetSymbolAddress((void**)&p_queryT, g_queryT);

    static int smem_set = 0;
    if (!smem_set) {
        cudaFuncSetAttribute(flash_kernel, cudaFuncAttributeMaxDynamicSharedMemorySize,
                             F_SMEM_BYTES);
        cudaFuncSetAttribute(pre_kernel, cudaFuncAttributeMaxDynamicSharedMemorySize,
                             PRE_SMEM);
        smem_set = 1;
    }

    // 1. ALL preprocessing in one launch (pipelined qproj + resize/k/v + Wp)
    pre_kernel<<<800, 256, PRE_SMEM>>>(query, ctx, Wq, bq, Wk, bk, Wv, bv, Wp);

    // 2. flash attention + residual + fused conv + GN stats -> F fp16
    flash_kernel<<<dim3(NHW / 128, NB), 256, F_SMEM_BYTES>>>(
        p_qT, p_kT, p_v, p_queryT, bp, p_F);

    // 3. group norm apply
    norm_kernel<<<(NB * NCQ * NHW) / 1024, 256>>>(gamma, beta, out);
}

// round 17
// speedup vs baseline: 1.0352x; 1.0352x over previous
#include <cuda_runtime.h>
#include <cuda_fp16.h>
#include <math.h>
#include <stdint.h>

#define NB 32
#define NCQ 256
#define NCC 3
#define NINTER 128
#define NHW 1024
#define NHC 224
#define GN_N (NCQ*NHW)

// ---------------- scratch (static device memory, no allocs) ----------------
__device__ __half g_qT[NB*NHW*NINTER];              // [b][i][c']
__device__ __half g_kT[NB*NHW*NINTER];              // [b][j][c']
__device__ __half g_v [NB*NCQ*NHW];                 // [b][c][j]
__device__ __half g_F [NB*NCQ*NHW];                 // fused F[b][o][i] (fp16)
__device__ __half g_queryT[NB*NHW*NCQ];             // [b][i][c]
__device__ __half g_Wp[NCQ*NCQ];
__device__ float  g_sums[NB*2];

__device__ __forceinline__ uint32_t pk2(float a, float b) {
    __half2 h = __floats2half2_rn(a, b);
    return *(uint32_t*)&h;
}
__device__ __forceinline__ float2 up2(uint32_t u) {
    __half2 h = *(__half2*)&u;
    return __half22float2(h);
}

__device__ __forceinline__ void mma_f16(float* d, uint32_t a0, uint32_t a1, uint32_t a2,
                                        uint32_t a3, uint32_t b0, uint32_t b1) {
    asm volatile(
        "mma.sync.aligned.m16n8k16.row.col.f32.f16.f16.f32 "
        "{%0,%1,%2,%3}, {%4,%5,%6,%7}, {%8,%9}, {%0,%1,%2,%3};"
        : "+f"(d[0]), "+f"(d[1]), "+f"(d[2]), "+f"(d[3])
        : "r"(a0), "r"(a1), "r"(a2), "r"(a3), "r"(b0), "r"(b1));
}

__device__ __forceinline__ void ldsm4(uint32_t& r0, uint32_t& r1, uint32_t& r2, uint32_t& r3,
                                      uint32_t adr) {
    asm volatile("ldmatrix.sync.aligned.m8n8.x4.shared.b16 {%0,%1,%2,%3}, [%4];"
                 : "=r"(r0), "=r"(r1), "=r"(r2), "=r"(r3) : "r"(adr));
}

__device__ __forceinline__ void cpa16(void* dst, const void* src) {
    uint32_t d = (uint32_t)__cvta_generic_to_shared(dst);
    asm volatile("cp.async.cg.shared.global [%0], [%1], 16;" :: "r"(d), "l"(src));
}
#define CP_COMMIT asm volatile("cp.async.commit_group;")

// ---------------- merged preprocessing kernel --------------------------------------
// sections: [0,256) qproj GEMM (+queryT emit); [256,768) resize+k/v; [768,800) Wp conv
#define HP 20   // smem row pitch in u32 (16 data + 4 pad)
__global__ __launch_bounds__(256)
void pre_kernel(const float* __restrict__ query, const float* __restrict__ ctx,
                const float* __restrict__ Wq, const float* __restrict__ bq,
                const float* __restrict__ Wk, const float* __restrict__ bk,
                const float* __restrict__ Wv, const float* __restrict__ bv,
                const float* __restrict__ Wp) {
    __shared__ uint32_t sm_u[2 * 128 * HP];
    int blk = blockIdx.x;
    int tid = threadIdx.x;

    if (blk < 256) {
        // qproj GEMM (M=128 i, N=128 c', K=256 c); A-tile register-prefetched.
        uint32_t* As = sm_u;
        uint32_t* Bs = sm_u + 128 * HP;
        int b = blk >> 3, i0 = (blk & 7) * 128;
        const float* qb = query + (size_t)b * NCQ * NHW;

        int lane = tid & 31, wid = tid >> 5;
        int wm = wid >> 2, wn = wid & 3;
        int gid = lane >> 2, tig = lane & 3;
        int lrow8 = (lane & 7) | (((lane >> 3) & 1) << 3);
        int kblk4 = (lane >> 4) << 2;
        uint32_t As0 = (uint32_t)__cvta_generic_to_shared(As);
        uint32_t Bs0 = (uint32_t)__cvta_generic_to_shared(Bs);

        float acc[4][4][4];
#pragma unroll
        for (int i = 0; i < 4; i++)
#pragma unroll
            for (int j = 0; j < 4; j++)
#pragma unroll
                for (int r = 0; r < 4; r++) acc[i][j][r] = 0.f;

        int m = tid & 127, kg = (tid >> 7) * 4;
        int qrow = tid >> 1, qcu = (tid & 1) * 8;
        uint32_t* qTout = (uint32_t*)(g_queryT + ((size_t)b * NHW + i0 + qrow) * NCQ) + qcu;

        float ar[4][4];
        // prefetch A tile 0
#pragma unroll
        for (int pass = 0; pass < 4; pass++) {
            int kb = pass * 8 + kg;
            const float* src = &qb[(size_t)kb * NHW + i0 + m];
            ar[pass][0] = src[0]; ar[pass][1] = src[NHW];
            ar[pass][2] = src[2 * NHW]; ar[pass][3] = src[3 * NHW];
        }

        for (int kt = 0; kt < 8; kt++) {
            __syncthreads();   // As/Bs free (mma kt-1 done)
            // store prefetched A
#pragma unroll
            for (int pass = 0; pass < 4; pass++) {
                int kb = pass * 8 + kg;
                As[m * HP + (kb >> 1)]     = pk2(ar[pass][0], ar[pass][1]);
                As[m * HP + (kb >> 1) + 1] = pk2(ar[pass][2], ar[pass][3]);
            }
            // B stage (Wq fp32 -> fp16), as R15
#pragma unroll
            for (int it = 0; it < 4; it++) {
                int id = tid + it * 256;
                int n = id >> 3, s4 = (id & 7) * 4;
                float4 wv = *(const float4*)&Wq[n * 256 + kt * 32 + s4];
                Bs[n * HP + (s4 >> 1)]     = pk2(wv.x, wv.y);
                Bs[n * HP + (s4 >> 1) + 1] = pk2(wv.z, wv.w);
            }
            __syncthreads();
            // prefetch A tile kt+1 (retires during mma below)
            if (kt < 7) {
#pragma unroll
                for (int pass = 0; pass < 4; pass++) {
                    int kb = pass * 8 + kg;
                    const float* src = &qb[(size_t)((kt + 1) * 32 + kb) * NHW + i0 + m];
                    ar[pass][0] = src[0]; ar[pass][1] = src[NHW];
                    ar[pass][2] = src[2 * NHW]; ar[pass][3] = src[3 * NHW];
                }
            }
            {   // emit transposed queryT tile (fp16) straight from As
                uint4 v0 = *(uint4*)&As[qrow * HP + qcu];
                uint4 v1 = *(uint4*)&As[qrow * HP + qcu + 4];
                *(uint4*)(qTout + kt * 16)     = v0;
                *(uint4*)(qTout + kt * 16 + 4) = v1;
            }
#pragma unroll
            for (int ks = 0; ks < 2; ks++) {
                int col = ks * 8 + kblk4;
                uint32_t afr[4][4], bfr[4][2];
#pragma unroll
                for (int mt = 0; mt < 4; mt++) {
                    int row = wm * 64 + mt * 16 + lrow8;
                    ldsm4(afr[mt][0], afr[mt][1], afr[mt][2], afr[mt][3],
                          As0 + (uint32_t)(row * HP + col) * 4);
                }
#pragma unroll
                for (int p = 0; p < 2; p++) {
                    int row = wn * 32 + p * 16 + lrow8;
                    ldsm4(bfr[2*p][0], bfr[2*p+1][0], bfr[2*p][1], bfr[2*p+1][1],
                          Bs0 + (uint32_t)(row * HP + col) * 4);
                }
#pragma unroll
                for (int mt = 0; mt < 4; mt++)
#pragma unroll
                    for (int nt = 0; nt < 4; nt++)
                        mma_f16(acc[mt][nt], afr[mt][0], afr[mt][1], afr[mt][2], afr[mt][3],
                                bfr[nt][0], bfr[nt][1]);
            }
        }
        uint32_t* C = (uint32_t*)(g_qT + ((size_t)b * NHW + i0) * NINTER);
#pragma unroll
        for (int mt = 0; mt < 4; mt++) {
#pragma unroll
            for (int nt = 0; nt < 4; nt++) {
                int row0 = wm * 64 + mt * 16 + gid;
                int col  = wn * 32 + nt * 8 + tig * 2;
                float bn0 = bq[col], bn1 = bq[col + 1];
#pragma unroll
                for (int h = 0; h < 2; h++) {
                    int row = row0 + h * 8;
                    C[(row * NINTER + col) >> 1] =
                        pk2(acc[mt][nt][h * 2] + bn0, acc[mt][nt][h * 2 + 1] + bn1);
                }
            }
        }
    } else if (blk < 768) {
        // resize + k/v projection
        float* sctx = (float*)sm_u;
        float* sWk  = sctx + 192;
        float* sbk  = sWk + 384;
        float* sWv  = sbk + 128;
        float* sbv  = sWv + 768;
        int s = blk - 256;
        int b = s >> 4, j0 = (s & 15) * 64;

        for (int i = tid; i < NINTER * 3; i += 256) sWk[i] = Wk[i];
        for (int i = tid; i < NCQ * 3; i += 256)    sWv[i] = Wv[i];
        if (tid < NINTER) sbk[tid] = bk[tid];
        if (tid < NCQ)    sbv[tid] = bv[tid];

        if (tid < NCC * 64) {
            int c = tid >> 6, jj = tid & 63;
            int p = j0 + jj;
            int y = p >> 5, x = p & 31;
            float sy = 7.f * y + 3.f;
            float sx = 7.f * x + 3.f;
            int y0 = (int)floorf(sy), x0 = (int)floorf(sx);
            float fy = sy - y0, fx = sx - x0;
            int y1 = min(y0 + 1, NHC - 1), x1 = min(x0 + 1, NHC - 1);
            y0 = max(y0, 0); x0 = max(x0, 0);
            const float* base = ctx + ((size_t)b * NCC + c) * NHC * NHC;
            float v00 = base[y0 * NHC + x0], v01 = base[y0 * NHC + x1];
            float v10 = base[y1 * NHC + x0], v11 = base[y1 * NHC + x1];
            sctx[c * 64 + jj] = (1.f - fy) * ((1.f - fx) * v00 + fx * v01)
                              + fy * ((1.f - fx) * v10 + fx * v11);
        }
        __syncthreads();

        __half* kout = g_kT + ((size_t)b * NHW + j0) * NINTER;
#pragma unroll 4
        for (int o = tid; o < 64 * NINTER; o += 256) {
            int jj = o >> 7, c = o & 127;
            kout[(size_t)jj * NINTER + c] = __float2half_rn(
                sbk[c] + sWk[c*3]*sctx[jj] + sWk[c*3+1]*sctx[64+jj] + sWk[c*3+2]*sctx[128+jj]);
        }
        __half* vout = g_v + (size_t)b * NCQ * NHW + j0;
#pragma unroll 4
        for (int o = tid; o < NCQ * 64; o += 256) {
            int c = o >> 6, jj = o & 63;
            vout[(size_t)c * NHW + jj] = __float2half_rn(
                sbv[c] + sWv[c*3]*sctx[jj] + sWv[c*3+1]*sctx[64+jj] + sWv[c*3+2]*sctx[128+jj]);
        }
    } else {
        // Wp convert + sums zero
        int base = (blk - 768) * 2048;
        for (int j = tid; j < 2048; j += 256)
            g_Wp[base + j] = __float2half_rn(Wp[base + j]);
        if (blk == 768 && tid < NB * 2) g_sums[tid] = 0.f;
    }
}

// ---------------- flash v6: attention + fused conv (Wp) in one kernel --------------
#define F_SMEM_BYTES (32768 * 4)

__global__ __launch_bounds__(256, 1)
void flash_kernel(const __half* __restrict__ qT, const __half* __restrict__ kT,
                  const __half* __restrict__ v, const __half* __restrict__ queryT,
                  const float* __restrict__ bp, __half* __restrict__ F) {
    extern __shared__ uint32_t smu[];
    uint32_t* Qs = smu;                    // 128 x 64
    uint32_t* Ks = Qs + 128 * 64;          // 2 x 64 x 64
    uint32_t* Vs = Ks + 2 * 64 * 64;       // 2 x 256 x 32
    uint32_t* WpS = smu;                   // epilogue: 2 x 256 x HP
    uint32_t* Xs  = smu + 2 * 256 * HP;    // epilogue: 128 x 128

    uint32_t Qs_b = (uint32_t)__cvta_generic_to_shared(Qs);
    uint32_t Ks_b = (uint32_t)__cvta_generic_to_shared(Ks);
    uint32_t Vs_b = (uint32_t)__cvta_generic_to_shared(Vs);
    uint32_t Wp_b = (uint32_t)__cvta_generic_to_shared(WpS);
    uint32_t Xs_b = (uint32_t)__cvta_generic_to_shared(Xs);

    int b = blockIdx.y, i0 = blockIdx.x * 128;
    const __half* qTb = qT + ((size_t)b * NHW + i0) * NINTER;
    const __half* kTb = kT + (size_t)b * NHW * NINTER;
    const __half* vb  = v  + (size_t)b * NCQ * NHW;

    int tid = threadIdx.x, lane = tid & 31, w = tid >> 5;
    int gid = lane >> 2, tig = lane & 3;
    int lrow8 = (lane & 7) | (((lane >> 3) & 1) << 3);
    int kblk4 = (lane >> 4) << 2;
    int swl = (lane & 7) << 2;

#pragma unroll
    for (int it = 0; it < 8; it++) {
        int id = tid + it * 256;
        int r = id >> 4, c4 = (id & 15) << 2;
        uint4 vq = *(const uint4*)&qTb[(size_t)r * NINTER + c4 * 2];
        *(uint4*)&Qs[r * 64 + (c4 ^ ((r & 7) << 2))] = vq;
    }

#pragma unroll
    for (int it = 0; it < 4; it++) {
        int id = tid + it * 256;
        int r = id >> 4, c4 = (id & 15) << 2;
        cpa16(&Ks[r * 64 + (c4 ^ ((r & 7) << 2))], &kTb[(size_t)r * NINTER + c4 * 2]);
    }
#pragma unroll
    for (int it = 0; it < 8; it++) {
        int id = tid + it * 256;
        int r = id >> 3, c4 = (id & 7) << 2;
        cpa16(&Vs[r * 32 + (c4 ^ ((r & 7) << 2))], &vb[(size_t)r * NHW + c4 * 2]);
    }
    CP_COMMIT;

    float oa[32][4];
#pragma unroll
    for (int nt = 0; nt < 32; nt++)
#pragma unroll
        for (int r = 0; r < 4; r++) oa[nt][r] = 0.f;
    float l0 = 0.f, l1 = 0.f, m0r = -1e30f, m1r = -1e30f;

    uint32_t qadr = Qs_b + (uint32_t)((w * 16 + lrow8) * 64) * 4;
    uint32_t kadr = Ks_b + (uint32_t)(lrow8 * 64) * 4;
    uint32_t vadr = Vs_b + (uint32_t)(lrow8 * 32) * 4;

    for (int t = 0; t < 16; t++) {
        int buf = t & 1;
        uint32_t kOff = (uint32_t)buf * (64 * 64 * 4);
        uint32_t vOff = (uint32_t)buf * (256 * 32 * 4);

        __syncthreads();
        if (t < 15) {
            int j0 = (t + 1) * 64;
            uint32_t* kd = &Ks[(buf ^ 1) * 64 * 64];
            uint32_t* vd = &Vs[(buf ^ 1) * 256 * 32];
#pragma unroll
            for (int it = 0; it < 4; it++) {
                int id = tid + it * 256;
                int r = id >> 4, c4 = (id & 15) << 2;
                cpa16(&kd[r * 64 + (c4 ^ ((r & 7) << 2))],
                      &kTb[(size_t)(j0 + r) * NINTER + c4 * 2]);
            }
#pragma unroll
            for (int it = 0; it < 8; it++) {
                int id = tid + it * 256;
                int r = id >> 3, c4 = (id & 7) << 2;
                cpa16(&vd[r * 32 + (c4 ^ ((r & 7) << 2))],
                      &vb[(size_t)r * NHW + j0 + c4 * 2]);
            }
            CP_COMMIT;
            asm volatile("cp.async.wait_group 1;");
        } else {
            asm volatile("cp.async.wait_group 0;");
        }
        __syncthreads();

        float sc[8][4];
#pragma unroll
        for (int nt = 0; nt < 8; nt++)
#pragma unroll
            for (int r = 0; r < 4; r++) sc[nt][r] = 0.f;
#pragma unroll
        for (int s = 0; s < 8; s++) {
            uint32_t cb = (uint32_t)(((s * 8 + kblk4) ^ swl) * 4);
            uint32_t a0, a1, a2, a3;
            ldsm4(a0, a1, a2, a3, qadr + cb);
#pragma unroll
            for (int g = 0; g < 4; g++) {
                uint32_t r0, r1, r2, r3;
                ldsm4(r0, r1, r2, r3, kadr + kOff + (uint32_t)(g * 16 * 64 * 4) + cb);
                mma_f16(sc[2*g],   a0, a1, a2, a3, r0, r2);
                mma_f16(sc[2*g+1], a0, a1, a2, a3, r1, r3);
            }
        }

        float mx0 = -1e30f, mx1 = -1e30f;
#pragma unroll
        for (int nt = 0; nt < 8; nt++) {
            mx0 = fmaxf(mx0, fmaxf(sc[nt][0], sc[nt][1]));
            mx1 = fmaxf(mx1, fmaxf(sc[nt][2], sc[nt][3]));
        }
        mx0 = fmaxf(mx0, __shfl_xor_sync(0xffffffffu, mx0, 1));
        mx0 = fmaxf(mx0, __shfl_xor_sync(0xffffffffu, mx0, 2));
        mx1 = fmaxf(mx1, __shfl_xor_sync(0xffffffffu, mx1, 1));
        mx1 = fmaxf(mx1, __shfl_xor_sync(0xffffffffu, mx1, 2));
        float mn0 = fmaxf(m0r, mx0), mn1 = fmaxf(m1r, mx1);
        float al0 = __expf(m0r - mn0), al1 = __expf(m1r - mn1);
        m0r = mn0; m1r = mn1;

        uint32_t pa[4][4];
        float s0 = 0.f, s1 = 0.f;
#pragma unroll
        for (int nt = 0; nt < 8; nt++) {
            float e0 = __expf(sc[nt][0] - mn0);
            float e1 = __expf(sc[nt][1] - mn0);
            float e2 = __expf(sc[nt][2] - mn1);
            float e3 = __expf(sc[nt][3] - mn1);
            s0 += e0 + e1; s1 += e2 + e3;
            pa[nt >> 1][(nt & 1) * 2]     = pk2(e0, e1);
            pa[nt >> 1][(nt & 1) * 2 + 1] = pk2(e2, e3);
        }
        l0 = l0 * al0 + s0;
        l1 = l1 * al1 + s1;

        if (al0 != 1.f || al1 != 1.f) {
#pragma unroll
            for (int nt = 0; nt < 32; nt++) {
                oa[nt][0] *= al0; oa[nt][1] *= al0;
                oa[nt][2] *= al1; oa[nt][3] *= al1;
            }
        }

#pragma unroll
        for (int k = 0; k < 4; k++) {
            uint32_t cb = (uint32_t)(((k * 8 + kblk4) ^ swl) * 4);
#pragma unroll
            for (int g = 0; g < 16; g++) {
                uint32_t r0, r1, r2, r3;
                ldsm4(r0, r1, r2, r3, vadr + vOff + (uint32_t)(g * 16 * 32 * 4) + cb);
                mma_f16(oa[2*g],   pa[k][0], pa[k][1], pa[k][2], pa[k][3], r0, r2);
                mma_f16(oa[2*g+1], pa[k][0], pa[k][1], pa[k][2], pa[k][3], r1, r3);
            }
        }
    }

    l0 += __shfl_xor_sync(0xffffffffu, l0, 1);
    l0 += __shfl_xor_sync(0xffffffffu, l0, 2);
    l1 += __shfl_xor_sync(0xffffffffu, l1, 1);
    l1 += __shfl_xor_sync(0xffffffffu, l1, 2);
    float inv0 = 1.f / l0, inv1 = 1.f / l1;

    // -------- stage X = O/l + residual into smem (fp16, XOR-swizzled) --------
    __syncthreads();
    {
        int r0 = w * 16 + gid, r1 = r0 + 8;
        const uint32_t* qres = (const uint32_t*)(queryT + ((size_t)b * NHW + i0) * NCQ);
        int x0m = (r0 & 7) << 2, x1m = (r1 & 7) << 2;
#pragma unroll
        for (int nt = 0; nt < 32; nt++) {
            int cu = nt * 4 + tig;
            float2 q0 = up2(qres[r0 * 128 + cu]);
            float2 q1 = up2(qres[r1 * 128 + cu]);
            Xs[r0 * 128 + (cu ^ x0m)] = pk2(oa[nt][0] * inv0 + q0.x, oa[nt][1] * inv0 + q0.y);
            Xs[r1 * 128 + (cu ^ x1m)] = pk2(oa[nt][2] * inv1 + q1.x, oa[nt][3] * inv1 + q1.y);
        }
    }
#pragma unroll
    for (int it = 0; it < 4; it++) {
        int id = tid + it * 256;
        int r = id >> 2, cs = (id & 3) * 4;
        cpa16(&WpS[r * HP + cs], g_Wp + r * 256 + cs * 2);
    }
    CP_COMMIT;
    asm volatile("cp.async.wait_group 0;");
    __syncthreads();

    // -------- inline GEMM: F[o][i0+i] = Wp[o][:] . X[i][:] + bp[o] --------
    int wm3 = w >> 1, wn3 = w & 1;
    float acc[4][8][4];
#pragma unroll
    for (int i = 0; i < 4; i++)
#pragma unroll
        for (int j = 0; j < 8; j++)
#pragma unroll
            for (int r = 0; r < 4; r++) acc[i][j][r] = 0.f;

    for (int kt = 0; kt < 8; kt++) {
        int buf = kt & 1;
        if (kt < 7) {
            uint32_t* wd = &WpS[(buf ^ 1) * 256 * HP];
            const __half* wsrc = g_Wp + (kt + 1) * 32;
#pragma unroll
            for (int it = 0; it < 4; it++) {
                int id = tid + it * 256;
                int r = id >> 2, cs = (id & 3) * 4;
                cpa16(&wd[r * HP + cs], wsrc + r * 256 + cs * 2);
            }
            CP_COMMIT;
        }
        uint32_t wBase = Wp_b + (uint32_t)(buf * 256 * HP) * 4;
#pragma unroll
        for (int ks = 0; ks < 2; ks++) {
            int colA = ks * 8 + kblk4;
            int colB = (kt * 16 + ks * 8 + kblk4) ^ swl;
            uint32_t afr[4][4], bfr[8][2];
#pragma unroll
            for (int mt = 0; mt < 4; mt++) {
                int row = wm3 * 64 + mt * 16 + lrow8;
                ldsm4(afr[mt][0], afr[mt][1], afr[mt][2], afr[mt][3],
                      wBase + (uint32_t)(row * HP + colA) * 4);
            }
#pragma unroll
            for (int p = 0; p < 4; p++) {
                int row = wn3 * 64 + p * 16 + lrow8;
                ldsm4(bfr[2*p][0], bfr[2*p+1][0], bfr[2*p][1], bfr[2*p+1][1],
                      Xs_b + (uint32_t)(row * 128 + colB) * 4);
            }
#pragma unroll
            for (int mt = 0; mt < 4; mt++)
#pragma unroll
                for (int nt = 0; nt < 8; nt++)
                    mma_f16(acc[mt][nt], afr[mt][0], afr[mt][1], afr[mt][2], afr[mt][3],
                            bfr[nt][0], bfr[nt][1]);
        }
        if (kt < 7) {
            asm volatile("cp.async.wait_group 0;");
            __syncthreads();
        }
    }

    // -------- epilogue: bias + GN stats + fp16 F store --------
    __shared__ float rs[8], rq[8];
    float ls = 0.f, lq = 0.f;
    __half* Fb = F + (size_t)b * NCQ * NHW + i0;
#pragma unroll
    for (int mt = 0; mt < 4; mt++) {
#pragma unroll
        for (int nt = 0; nt < 8; nt++) {
            int row0 = wm3 * 64 + mt * 16 + gid;
            int col  = wn3 * 64 + nt * 8 + tig * 2;
#pragma unroll
            for (int h = 0; h < 2; h++) {
                int row = row0 + h * 8;
                float bm = bp[row];
                float x = acc[mt][nt][h * 2] + bm, y = acc[mt][nt][h * 2 + 1] + bm;
                ls += x + y; lq += x * x + y * y;
                *(uint32_t*)(Fb + (size_t)row * NHW + col) = pk2(x, y);
            }
        }
    }
#pragma unroll
    for (int o = 16; o; o >>= 1) {
        ls += __shfl_xor_sync(0xffffffffu, ls, o);
        lq += __shfl_xor_sync(0xffffffffu, lq, o);
    }
    if (lane == 0) { rs[w] = ls; rq[w] = lq; }
    __syncthreads();
    if (tid == 0) {
        float ts = 0.f, tq = 0.f;
#pragma unroll
        for (int i = 0; i < 8; i++) { ts += rs[i]; tq += rq[i]; }
        atomicAdd(&g_sums[b * 2], ts);
        atomicAdd(&g_sums[b * 2 + 1], tq);
    }
}

// ---------------- normalize + affine -> out (half F in, float4 out) -----------------
__global__ void norm_kernel(const float* __restrict__ gamma, const float* __restrict__ beta,
                            float* __restrict__ out) {
    int idx = (blockIdx.x * blockDim.x + threadIdx.x) * 4;
    int b = idx >> 18;
    int o = (idx >> 10) & 255;
    float s = g_sums[b * 2], s2 = g_sums[b * 2 + 1];
    const float n = (float)GN_N;
    float mu = s / n;
    float var = s2 / n - mu * mu;
    float rstd = rsqrtf(var + 1e-5f);
    float ga = gamma[o] * rstd, be = beta[o] - mu * ga;
    uint2 fh = *(const uint2*)&((const uint32_t*)g_F)[idx >> 1];
    float2 f01 = up2(fh.x), f23 = up2(fh.y);
    float4 r;
    r.x = f01.x * ga + be; r.y = f01.y * ga + be;
    r.z = f23.x * ga + be; r.w = f23.y * ga + be;
    *(float4*)&out[idx] = r;
}

// ---------------- launch --------------------------------------------------------------
extern "C" void kernel_launch(void* const* d_in, const int* in_sizes, int n_in,
                              void* d_out, int out_size) {
    const float* query = (const float*)d_in[0];
    const float* ctx   = (const float*)d_in[1];
    const float* Wq = (const float*)d_in[2];  const float* bq = (const float*)d_in[3];
    const float* Wk = (const float*)d_in[4];  const float* bk = (const float*)d_in[5];
    const float* Wv = (const float*)d_in[6];  const float* bv = (const float*)d_in[7];
    const float* Wp = (const float*)d_in[8];  const float* bp = (const float*)d_in[9];
    const float* gamma = (const float*)d_in[10];
    const float* beta  = (const float*)d_in[11];
    float* out = (float*)d_out;

    __half *p_qT, *p_kT, *p_v, *p_queryT, *p_F;
    cudaGetSymbolAddress((void**)&p_qT, g_qT);
    cudaGetSymbolAddress((void**)&p_kT, g_kT);
    cudaGetSymbolAddress((void**)&p_v, g_v);
    cudaGetSymbolAddress((void**)&p_F, g_F);
    cudaGetSymbolAddress((void**)&p_queryT, g_queryT);

    static int smem_set = 0;
    if (!smem_set) {
        cudaFuncSetAttribute(flash_kernel, cudaFuncAttributeMaxDynamicSharedMemorySize,
                             F_SMEM_BYTES);
        smem_set = 1;
    }

    // 1. ALL preprocessing in one launch (static 20KB smem; A-prefetched qproj)
    pre_kernel<<<800, 256>>>(query, ctx, Wq, bq, Wk, bk, Wv, bv, Wp);

    // 2. flash attention + residual + fused conv + GN stats -> F fp16
    flash_kernel<<<dim3(NHW / 128, NB), 256, F_SMEM_BYTES>>>(
        p_qT, p_kT, p_v, p_queryT, bp, p_F);

    // 3. group norm apply
    norm_kernel<<<(NB * NCQ * NHW) / 1024, 256>>>(gamma, beta, out);
}